// round 4
// baseline (speedup 1.0000x reference)
#include <cuda_runtime.h>
#include <cuda_bf16.h>
#include <cstdint>

// Problem constants (fixed by the dataset)
#define PB    2        // batch
#define PT    10000    // nodes
#define PM    100000   // edges
#define PD    128      // feature dim
#define PDOUT 128      // output dim

// Pristine BIAS-FREE copy of x @ W^T (B, T, 2, DOUT) — scatter reads this
// while atomics mutate d_out. 2*10000*2*128 floats = 20.48 MB.
__device__ float g_y[PB * PT * 2 * PDOUT];

// ---------------------------------------------------------------------------
// Kernel 1: for all 40,000 rows (B*T*2, D):
//   ycopy[row][o] = sum_d x[row][d] * W[o][d]        (NO bias)
//   out[row][o]   = ycopy[row][o] + bias[o]
// Each thread owns one output column o, keeping W row o in registers
// (32 float4 = 128 regs). 32 input rows staged in smem per block; smem
// reads are warp-uniform broadcasts (conflict-free).
// ---------------------------------------------------------------------------
#define ROWS_PER_BLOCK 32

__global__ __launch_bounds__(128) void gemm_bias_kernel(
    const float* __restrict__ x,     // (B*T*2, 128)
    const float* __restrict__ W,     // (128, 128) row-major (DOUT, D)
    const float* __restrict__ bias,  // (128,)
    float* __restrict__ out,         // d_out (B*T*2, 128)  = y + bias
    float* __restrict__ ycopy)       // g_y   (B*T*2, 128)  = y (no bias)
{
    __shared__ float xs[ROWS_PER_BLOCK][PD];
    const int tid  = threadIdx.x;          // output column o
    const int row0 = blockIdx.x * ROWS_PER_BLOCK;

    // W row o -> registers
    float4 w4[32];
    const float4* Wv = reinterpret_cast<const float4*>(W + tid * PD);
#pragma unroll
    for (int i = 0; i < 32; i++) w4[i] = Wv[i];
    const float bv = bias[tid];

    // Stage 32 rows of x (coalesced)
#pragma unroll
    for (int r = 0; r < ROWS_PER_BLOCK; r++)
        xs[r][tid] = x[(size_t)(row0 + r) * PD + tid];
    __syncthreads();

    for (int r = 0; r < ROWS_PER_BLOCK; r++) {
        const float4* xv = reinterpret_cast<const float4*>(xs[r]);
        float acc0 = 0.f, acc1 = 0.f;
#pragma unroll
        for (int i = 0; i < 32; i += 2) {
            float4 xa = xv[i],     wa = w4[i];
            float4 xb = xv[i + 1], wb = w4[i + 1];
            acc0 += xa.x * wa.x + xa.y * wa.y + xa.z * wa.z + xa.w * wa.w;
            acc1 += xb.x * wb.x + xb.y * wb.y + xb.z * wb.z + xb.w * wb.w;
        }
        const float v = acc0 + acc1;           // bias-free
        const size_t o = (size_t)(row0 + r) * PD + tid;
        ycopy[o] = v;
        out[o]   = v + bv;
    }
}

// ---------------------------------------------------------------------------
// Kernel 2: scatter. One warp per (b, m, c) unit: 400,000 warps total.
// dst_row = node_in[m], src_row = node_out[m]:
//   d_out[b, node_in, c, :] += A[b,m] * g_y[b, node_out, c, :]
// Each lane handles 4 consecutive floats: float4 gather + one vector
// atomicAdd(float4) (sm_90+ native -> RED.E.ADD.F32X4).
// ---------------------------------------------------------------------------
__global__ __launch_bounds__(256) void scatter_kernel(
    const int*   __restrict__ edge,  // (2, M): [0..M) = node_in, [M..2M) = node_out
    const float* __restrict__ A,     // (B, M)
    float*       __restrict__ out)   // d_out
{
    const unsigned wg   = blockIdx.x * 8u + (threadIdx.x >> 5);
    const int      lane = threadIdx.x & 31;
    if (wg >= (unsigned)(PB * 2 * PM)) return;

    const unsigned m  = wg % PM;
    const unsigned bc = wg / PM;          // b*2 + c
    const unsigned b  = bc >> 1;
    const unsigned c  = bc & 1;

    const int   ni = __ldg(edge + m);         // node_in
    const int   no = __ldg(edge + PM + m);    // node_out
    const float wv = __ldg(A + (size_t)b * PM + m);

    const size_t src_off = ((size_t)((b * PT + (unsigned)no) * 2 + c)) << 7;  // *128
    const size_t dst_off = ((size_t)((b * PT + (unsigned)ni) * 2 + c)) << 7;

    const float4 v = reinterpret_cast<const float4*>(g_y + src_off)[lane];
    float4* dst = reinterpret_cast<float4*>(out + dst_off) + lane;
    atomicAdd(dst, make_float4(v.x * wv, v.y * wv, v.z * wv, v.w * wv));
}

// ---------------------------------------------------------------------------
// Launch: inputs per metadata order:
//   d_in[0] x_1st (B,T,2,D) f32       d_in[1] x_2nd (UNUSED)
//   d_in[2] edge (2,M) i32            d_in[3] A_masked (B,1,M) f32
//   d_in[4] W (DOUT,D) f32            d_in[5] b (DOUT,) f32
// ---------------------------------------------------------------------------
extern "C" void kernel_launch(void* const* d_in, const int* in_sizes, int n_in,
                              void* d_out, int out_size)
{
    const float* x1   = (const float*)d_in[0];
    const int*   edge = (const int*)  d_in[2];
    const float* A    = (const float*)d_in[3];
    const float* W    = (const float*)d_in[4];
    const float* bias = (const float*)d_in[5];
    float*       out  = (float*)d_out;

    float* ycopy = nullptr;
    cudaGetSymbolAddress((void**)&ycopy, g_y);

    const int total_rows = PB * PT * 2;                 // 40000
    gemm_bias_kernel<<<total_rows / ROWS_PER_BLOCK, 128>>>(x1, W, bias, out, ycopy);

    const unsigned units  = PB * 2 * PM;                // 400000 warps
    const unsigned blocks = (units + 7) / 8;            // 8 warps / block
    scatter_kernel<<<blocks, 256>>>(edge, A, out);
}

// round 6
// speedup vs baseline: 1.0156x; 1.0156x over previous
#include <cuda_runtime.h>
#include <cuda_bf16.h>
#include <cstdint>

#define PB    2
#define PT    10000
#define PM    100000
#define PD    128
#define PDOUT 128
#define NROWS (PB * PT * 2)   // 40000

// Scratch (device globals — no allocation allowed)
__device__ float g_y[NROWS * PDOUT];       // bias-free x@W^T, 20.48 MB
__device__ float g_Wt[PD * PDOUT];         // W transposed (d, o)
__device__ int   g_counts[PT];
__device__ int   g_offsets[PT + 1];
__device__ int   g_cursor[PT];
__device__ int   g_eidx[PM];               // edge ids sorted by node_in

// ---------------------------------------------------------------------------
// W transpose: Wt[d][o] = W[o][d]
// ---------------------------------------------------------------------------
__global__ __launch_bounds__(256) void transpose_w_kernel(
    const float* __restrict__ W, float* __restrict__ Wt)
{
    int idx = blockIdx.x * 256 + threadIdx.x;      // 16384 total
    int o = idx >> 7, d = idx & 127;
    Wt[d * PDOUT + o] = W[idx];
}

// ---------------------------------------------------------------------------
// GEMM: y[row][o] = sum_d x[row][d] * Wt[d][o]   (bias-free, writes g_y only)
// 128x128 tile per block, 256 threads (16x16), 8x8 register tile per thread.
// ---------------------------------------------------------------------------
#define BM 128
#define BK 16

__global__ __launch_bounds__(256) void gemm_kernel(
    const float* __restrict__ x,      // (NROWS, 128)
    const float* __restrict__ Wt,     // (128, 128) = (d, o)
    float* __restrict__ y)            // g_y
{
    __shared__ float  xs[BM][20];          // row-major, pad 20 (mod 4 = 0)
    __shared__ float4 ws[BK][32];          // k-major: ws[k][o/4]

    const int tid = threadIdx.x;
    const int tx  = tid & 15;              // col group: cols tx*8 .. tx*8+7
    const int ty  = tid >> 4;              // row group: rows ty*8 .. ty*8+7
    const int row0 = blockIdx.x * BM;

    float acc[8][8];
#pragma unroll
    for (int i = 0; i < 8; i++)
#pragma unroll
        for (int j = 0; j < 8; j++) acc[i][j] = 0.f;

    for (int k0 = 0; k0 < PD; k0 += BK) {
        // Stage x tile: 128 rows x 16 k = 512 float4, 2 per thread
        {
            int f4 = tid * 2;
#pragma unroll
            for (int u = 0; u < 2; u++, f4++) {
                int r = f4 >> 2, kq = (f4 & 3) * 4;
                int grow = row0 + r;
                float4 v = make_float4(0.f, 0.f, 0.f, 0.f);
                if (grow < NROWS)
                    v = *(const float4*)(x + (size_t)grow * PD + k0 + kq);
                *(float4*)&xs[r][kq] = v;
            }
        }
        // Stage W tile: 16 k x 128 o = 512 float4, 2 per thread (coalesced)
        {
            int f4 = tid * 2;
#pragma unroll
            for (int u = 0; u < 2; u++, f4++) {
                int kk = f4 >> 5, cq = f4 & 31;
                ws[kk][cq] = *(const float4*)(Wt + (size_t)(k0 + kk) * PDOUT + cq * 4);
            }
        }
        __syncthreads();

#pragma unroll
        for (int kk = 0; kk < BK; kk++) {
            float xr[8];
#pragma unroll
            for (int i = 0; i < 8; i++) xr[i] = xs[ty * 8 + i][kk];
            float4 wa = ws[kk][tx * 2];
            float4 wb = ws[kk][tx * 2 + 1];
            float wr[8] = {wa.x, wa.y, wa.z, wa.w, wb.x, wb.y, wb.z, wb.w};
#pragma unroll
            for (int i = 0; i < 8; i++)
#pragma unroll
                for (int j = 0; j < 8; j++)
                    acc[i][j] += xr[i] * wr[j];
        }
        __syncthreads();
    }

    // Write back (bias-free)
#pragma unroll
    for (int i = 0; i < 8; i++) {
        int grow = row0 + ty * 8 + i;
        if (grow >= NROWS) break;
        float* dst = y + (size_t)grow * PDOUT + tx * 8;
        *(float4*)(dst)     = make_float4(acc[i][0], acc[i][1], acc[i][2], acc[i][3]);
        *(float4*)(dst + 4) = make_float4(acc[i][4], acc[i][5], acc[i][6], acc[i][7]);
    }
}

// ---------------------------------------------------------------------------
// CSR build over node_in
// ---------------------------------------------------------------------------
__global__ __launch_bounds__(256) void hist_kernel(const int* __restrict__ edge)
{
    int m = blockIdx.x * 256 + threadIdx.x;
    if (m < PM) atomicAdd(&g_counts[edge[m]], 1);
}

__global__ __launch_bounds__(1024) void scan_kernel()
{
    __shared__ int tot[1024];
    const int tid = threadIdx.x;
    const int base = tid * 10;            // 1024*10 >= PT
    int loc[10];
    int sum = 0;
#pragma unroll
    for (int i = 0; i < 10; i++) {
        int idx = base + i;
        int v = (idx < PT) ? g_counts[idx] : 0;
        loc[i] = sum;
        sum += v;
    }
    tot[tid] = sum;
    __syncthreads();
    for (int off = 1; off < 1024; off <<= 1) {
        int v = 0;
        if (tid >= off) v = tot[tid - off];
        __syncthreads();
        if (tid >= off) tot[tid] += v;
        __syncthreads();
    }
    int ex = (tid == 0) ? 0 : tot[tid - 1];
#pragma unroll
    for (int i = 0; i < 10; i++) {
        int idx = base + i;
        if (idx < PT) {
            g_offsets[idx] = ex + loc[i];
            g_cursor[idx]  = ex + loc[i];
        }
    }
    if (tid == 1023) g_offsets[PT] = tot[1023];   // == PM
}

__global__ __launch_bounds__(256) void fill_kernel(const int* __restrict__ edge)
{
    int m = blockIdx.x * 256 + threadIdx.x;
    if (m < PM) {
        int t = edge[m];                       // node_in
        int pos = atomicAdd(&g_cursor[t], 1);
        g_eidx[pos] = m;
    }
}

// ---------------------------------------------------------------------------
// Gather-reduce: one warp per output row u = ((b*PT + t)*2 + c).
//   out[u] = g_y[u] + bias + sum_{e in CSR[t]} A[b,e] * g_y[(b*PT+no[e])*2+c]
// Each lane owns 4 consecutive floats (float4).
// ---------------------------------------------------------------------------
__global__ __launch_bounds__(256) void gather_kernel(
    const int*   __restrict__ edge,   // (2, M)
    const float* __restrict__ A,      // (B, M)
    const float* __restrict__ bias,   // (128,)
    const float* __restrict__ y,      // g_y
    float*       __restrict__ out)
{
    const unsigned u = blockIdx.x * 8u + (threadIdx.x >> 5);   // 0..NROWS-1, exact
    const int lane = threadIdx.x & 31;

    const unsigned c  = u & 1;
    const unsigned bt = u >> 1;
    const unsigned t  = bt % PT;
    const unsigned b  = bt / PT;

    float4 acc = ((const float4*)(y + ((size_t)u << 7)))[lane];
    const float4 b4 = ((const float4*)bias)[lane];
    acc.x += b4.x; acc.y += b4.y; acc.z += b4.z; acc.w += b4.w;

    const int s = g_offsets[t];
    const int e = g_offsets[t + 1];
    for (int p = s; p < e; p++) {
        const int   m  = g_eidx[p];
        const int   no = __ldg(edge + PM + m);
        const float wv = __ldg(A + (size_t)b * PM + m);
        const size_t src = ((size_t)(((b * PT + (unsigned)no) << 1) | c)) << 7;
        const float4 v = ((const float4*)(y + src))[lane];
        acc.x += wv * v.x; acc.y += wv * v.y;
        acc.z += wv * v.z; acc.w += wv * v.w;
    }

    ((float4*)out)[((size_t)u << 5) + lane] = acc;
}

// ---------------------------------------------------------------------------
// Launch. Inputs: [0] x_1st, [1] x_2nd (unused), [2] edge, [3] A_masked,
//                 [4] W, [5] b
// ---------------------------------------------------------------------------
extern "C" void kernel_launch(void* const* d_in, const int* in_sizes, int n_in,
                              void* d_out, int out_size)
{
    const float* x1   = (const float*)d_in[0];
    const int*   edge = (const int*)  d_in[2];
    const float* A    = (const float*)d_in[3];
    const float* W    = (const float*)d_in[4];
    const float* bias = (const float*)d_in[5];
    float*       out  = (float*)d_out;

    float* y = nullptr;  cudaGetSymbolAddress((void**)&y,  g_y);
    float* Wt = nullptr; cudaGetSymbolAddress((void**)&Wt, g_Wt);
    int* counts = nullptr; cudaGetSymbolAddress((void**)&counts, g_counts);

    cudaMemsetAsync(counts, 0, PT * sizeof(int));

    transpose_w_kernel<<<(PD * PDOUT) / 256, 256>>>(W, Wt);

    const int gemm_blocks = (NROWS + BM - 1) / BM;       // 313
    gemm_kernel<<<gemm_blocks, 256>>>(x1, Wt, y);

    hist_kernel<<<(PM + 255) / 256, 256>>>(edge);
    scan_kernel<<<1, 1024>>>();
    fill_kernel<<<(PM + 255) / 256, 256>>>(edge);

    gather_kernel<<<NROWS / 8, 256>>>(edge, A, bias, y, out);
}

// round 8
// speedup vs baseline: 1.5899x; 1.5655x over previous
#include <cuda_runtime.h>
#include <cuda_bf16.h>
#include <cstdint>

#define PB    2
#define PT    10000
#define PM    100000
#define PD    128
#define PDOUT 128
#define NROWS (PB * PT * 2)   // 40000

#define WPAD 136              // padded row length (bf16 elems) -> 272 B, conflict-free ldmatrix

// ---------------------------------------------------------------------------
// Device scratch (no allocation allowed)
// ---------------------------------------------------------------------------
__device__ float g_y[NROWS * PDOUT];                       // bias-free x@W^T (20.48 MB)
__device__ __align__(16) __nv_bfloat16 g_Whi[PDOUT * WPAD];  // W hi, padded rows
__device__ __align__(16) __nv_bfloat16 g_Wlo[PDOUT * WPAD];  // W lo
__device__ int g_counts[PT];
__device__ int g_offsets[PT + 1];
__device__ int g_cursor[PT];
__device__ int g_eidx[PM];

// ---------------------------------------------------------------------------
// Warp MMA helpers (sm_80-baseline -> valid in family-generic compute_103 PTX)
// ---------------------------------------------------------------------------
__device__ __forceinline__ uint32_t smem_u32(const void* p) {
    uint32_t a;
    asm("{ .reg .u64 t; cvta.to.shared.u64 t, %1; cvt.u32.u64 %0, t; }" : "=r"(a) : "l"(p));
    return a;
}
__device__ __forceinline__ void ldsm_x4(uint32_t* r, uint32_t addr) {
    asm volatile("ldmatrix.sync.aligned.m8n8.x4.shared.b16 {%0,%1,%2,%3}, [%4];"
                 : "=r"(r[0]), "=r"(r[1]), "=r"(r[2]), "=r"(r[3]) : "r"(addr));
}
__device__ __forceinline__ void ldsm_x2(uint32_t* r, uint32_t addr) {
    asm volatile("ldmatrix.sync.aligned.m8n8.x2.shared.b16 {%0,%1}, [%2];"
                 : "=r"(r[0]), "=r"(r[1]) : "r"(addr));
}
__device__ __forceinline__ void mma_bf16(float* c, const uint32_t* a, const uint32_t* b) {
    asm volatile("mma.sync.aligned.m16n8k16.row.col.f32.bf16.bf16.f32 "
                 "{%0,%1,%2,%3}, {%4,%5,%6,%7}, {%8,%9}, {%0,%1,%2,%3};"
                 : "+f"(c[0]), "+f"(c[1]), "+f"(c[2]), "+f"(c[3])
                 : "r"(a[0]), "r"(a[1]), "r"(a[2]), "r"(a[3]), "r"(b[0]), "r"(b[1]));
}

// ---------------------------------------------------------------------------
// Prep: split W (128x128 f32) into bf16 hi/lo padded-row images.
// ---------------------------------------------------------------------------
__global__ __launch_bounds__(256) void prep_kernel(const float* __restrict__ W)
{
    int idx = blockIdx.x * 256 + threadIdx.x;          // < 16384
    int o = idx >> 7, d = idx & 127;
    float w = W[idx];
    __nv_bfloat16 hi = __float2bfloat16(w);
    __nv_bfloat16 lo = __float2bfloat16(w - __bfloat162float(hi));
    g_Whi[o * WPAD + d] = hi;
    g_Wlo[o * WPAD + d] = lo;
}

// ---------------------------------------------------------------------------
// GEMM: y = x @ W^T via mma.sync bf16 split (hi*hi + hi*lo + lo*hi).
// Block = 256 thr (8 warps) computes 128 rows x 128 cols, full K=128 in smem.
// Warp w: rows (w&1)*64..+63, cols (w>>2? no: w>>1)*32..+31.
// ---------------------------------------------------------------------------
#define SM_XHI 0
#define SM_XLO 34816          // 128*272
#define SM_WHI 69632
#define SM_WLO 104448
#define GEMM_SMEM 139264

__global__ __launch_bounds__(256, 1) void mma_gemm_kernel(
    const float* __restrict__ x, float* __restrict__ y)
{
    extern __shared__ char smem[];
    const uint32_t sb = smem_u32(smem);
    const int tid = threadIdx.x, wid = tid >> 5, lane = tid & 31;
    const int row0 = blockIdx.x * 128;

    // ---- Stage W images (linear copy of 34816 B each = 2176 uint4) ----
    {
        const uint4* shi = (const uint4*)g_Whi;
        const uint4* slo = (const uint4*)g_Wlo;
        uint4* dhi = (uint4*)(smem + SM_WHI);
        uint4* dlo = (uint4*)(smem + SM_WLO);
#pragma unroll
        for (int i = tid; i < 2176; i += 256) { dhi[i] = shi[i]; dlo[i] = slo[i]; }
    }

    // ---- Stage + convert x tile: 128 rows x 128 cols (f32 -> bf16 hi/lo) ----
    {
#pragma unroll
        for (int i = 0; i < 16; i++) {
            const int idx = i * 256 + tid;             // float4 index
            const int r = idx >> 5, q = idx & 31;      // row, quad-col
            const int grow = row0 + r;
            float4 v = make_float4(0.f, 0.f, 0.f, 0.f);
            if (grow < NROWS) v = *(const float4*)(x + (size_t)grow * PD + q * 4);

            __nv_bfloat162 h01 = __float22bfloat162_rn(make_float2(v.x, v.y));
            __nv_bfloat162 h23 = __float22bfloat162_rn(make_float2(v.z, v.w));
            float2 f01 = __bfloat1622float2(h01);
            float2 f23 = __bfloat1622float2(h23);
            __nv_bfloat162 l01 = __float22bfloat162_rn(make_float2(v.x - f01.x, v.y - f01.y));
            __nv_bfloat162 l23 = __float22bfloat162_rn(make_float2(v.z - f23.x, v.w - f23.y));

            const int boff = r * 272 + q * 8;
            *(uint2*)(smem + SM_XHI + boff) = make_uint2(*(uint32_t*)&h01, *(uint32_t*)&h23);
            *(uint2*)(smem + SM_XLO + boff) = make_uint2(*(uint32_t*)&l01, *(uint32_t*)&l23);
        }
    }
    __syncthreads();

    // ---- Mainloop ----
    const int wm = wid & 1;            // 2 warps along M
    const int wn = wid >> 1;           // 4 warps along N
    const int m_base = wm * 64;
    const int n_base = wn * 32;

    float acc[4][4][4];
#pragma unroll
    for (int mt = 0; mt < 4; mt++)
#pragma unroll
        for (int nt = 0; nt < 4; nt++)
#pragma unroll
            for (int j = 0; j < 4; j++) acc[mt][nt][j] = 0.f;

    const int g  = lane >> 3;          // ldmatrix address group
    const int lr = lane & 7;

#pragma unroll
    for (int ks = 0; ks < 8; ks++) {
        const int k0 = ks * 16;

        // B fragments: 4 n-tiles, hi & lo. n8k16 frag via ldmatrix.x2 (non-trans).
        uint32_t bh[4][2], bl[4][2];
#pragma unroll
        for (int nt = 0; nt < 4; nt++) {
            const int nrow = n_base + nt * 8 + lr;
            const int ncol = k0 + ((lane >> 3) & 1) * 8;
            const uint32_t off = (uint32_t)(nrow * 272 + ncol * 2);
            ldsm_x2(bh[nt], sb + SM_WHI + off);
            ldsm_x2(bl[nt], sb + SM_WLO + off);
        }

#pragma unroll
        for (int mt = 0; mt < 4; mt++) {
            // A fragment m16k16 via ldmatrix.x4
            const int arow = m_base + mt * 16 + (g & 1) * 8 + lr;
            const int acol = k0 + (g >> 1) * 8;
            const uint32_t off = (uint32_t)(arow * 272 + acol * 2);
            uint32_t ah[4], al[4];
            ldsm_x4(ah, sb + SM_XHI + off);
            ldsm_x4(al, sb + SM_XLO + off);
#pragma unroll
            for (int nt = 0; nt < 4; nt++) {
                mma_bf16(acc[mt][nt], ah, bh[nt]);
                mma_bf16(acc[mt][nt], ah, bl[nt]);
                mma_bf16(acc[mt][nt], al, bh[nt]);
            }
        }
    }

    // ---- Epilogue: c0,c1 -> row (lane>>2), cols (lane&3)*2; c2,c3 -> row+8 ----
    const int erow = m_base + (lane >> 2);
    const int ecol = (lane & 3) * 2;
#pragma unroll
    for (int mt = 0; mt < 4; mt++) {
        const int r0 = row0 + erow + mt * 16;
#pragma unroll
        for (int nt = 0; nt < 4; nt++) {
            const int col = n_base + nt * 8 + ecol;
            if (r0 < NROWS)
                *(float2*)(y + (size_t)r0 * PDOUT + col) =
                    make_float2(acc[mt][nt][0], acc[mt][nt][1]);
            if (r0 + 8 < NROWS)
                *(float2*)(y + (size_t)(r0 + 8) * PDOUT + col) =
                    make_float2(acc[mt][nt][2], acc[mt][nt][3]);
        }
    }
}

// ---------------------------------------------------------------------------
// CSR build over node_in
// ---------------------------------------------------------------------------
__global__ __launch_bounds__(256) void hist_kernel(const int* __restrict__ edge)
{
    int m = blockIdx.x * 256 + threadIdx.x;
    if (m < PM) atomicAdd(&g_counts[edge[m]], 1);
}

__global__ __launch_bounds__(1024) void scan_kernel()
{
    const int tid = threadIdx.x, lane = tid & 31, wid = tid >> 5;
    const int base = tid * 10;
    int loc[10];
    int s = 0;
#pragma unroll
    for (int i = 0; i < 10; i++) {
        int idx = base + i;
        int v = (idx < PT) ? g_counts[idx] : 0;
        loc[i] = s; s += v;
    }
    int inc = s;
#pragma unroll
    for (int d = 1; d < 32; d <<= 1) {
        int n = __shfl_up_sync(0xffffffffu, inc, d);
        if (lane >= d) inc += n;
    }
    __shared__ int wsum[32];
    if (lane == 31) wsum[wid] = inc;
    __syncthreads();
    if (wid == 0) {
        int w = wsum[lane];
#pragma unroll
        for (int d = 1; d < 32; d <<= 1) {
            int n = __shfl_up_sync(0xffffffffu, w, d);
            if (lane >= d) w += n;
        }
        wsum[lane] = w;
    }
    __syncthreads();
    const int pre = (wid ? wsum[wid - 1] : 0) + (inc - s);
#pragma unroll
    for (int i = 0; i < 10; i++) {
        int idx = base + i;
        if (idx < PT) { g_offsets[idx] = pre + loc[i]; g_cursor[idx] = pre + loc[i]; }
    }
    if (tid == 1023) g_offsets[PT] = wsum[31];
}

__global__ __launch_bounds__(256) void fill_kernel(const int* __restrict__ edge)
{
    int m = blockIdx.x * 256 + threadIdx.x;
    if (m < PM) {
        int pos = atomicAdd(&g_cursor[edge[m]], 1);
        g_eidx[pos] = m;
    }
}

// ---------------------------------------------------------------------------
// Gather-reduce: one warp per output row u = ((b*PT + t)*2 + c).
//   out[u] = g_y[u] + bias + sum_{e in CSR[t]} A[b,e] * g_y[(b*PT+no[e])*2+c]
// ---------------------------------------------------------------------------
__global__ __launch_bounds__(256) void gather_kernel(
    const int*   __restrict__ edge,
    const float* __restrict__ A,
    const float* __restrict__ bias,
    const float* __restrict__ y,
    float*       __restrict__ out)
{
    const unsigned u = blockIdx.x * 8u + (threadIdx.x >> 5);
    const int lane = threadIdx.x & 31;

    const unsigned c  = u & 1;
    const unsigned bt = u >> 1;
    const unsigned t  = bt % PT;
    const unsigned b  = bt / PT;

    float4 acc = ((const float4*)(y + ((size_t)u << 7)))[lane];
    const float4 b4 = ((const float4*)bias)[lane];
    acc.x += b4.x; acc.y += b4.y; acc.z += b4.z; acc.w += b4.w;

    const int s = g_offsets[t];
    const int e = g_offsets[t + 1];
    for (int p = s; p < e; p++) {
        const int   m  = g_eidx[p];
        const int   no = __ldg(edge + PM + m);
        const float wv = __ldg(A + (size_t)b * PM + m);
        const size_t src = ((size_t)(((b * PT + (unsigned)no) << 1) | c)) << 7;
        const float4 v = ((const float4*)(y + src))[lane];
        acc.x += wv * v.x; acc.y += wv * v.y;
        acc.z += wv * v.z; acc.w += wv * v.w;
    }
    ((float4*)out)[((size_t)u << 5) + lane] = acc;
}

// ---------------------------------------------------------------------------
// Launch. Inputs: [0] x_1st, [1] x_2nd (unused), [2] edge, [3] A_masked,
//                 [4] W, [5] b
// ---------------------------------------------------------------------------
extern "C" void kernel_launch(void* const* d_in, const int* in_sizes, int n_in,
                              void* d_out, int out_size)
{
    const float* x1   = (const float*)d_in[0];
    const int*   edge = (const int*)  d_in[2];
    const float* A    = (const float*)d_in[3];
    const float* W    = (const float*)d_in[4];
    const float* bias = (const float*)d_in[5];
    float*       out  = (float*)d_out;

    float* y = nullptr;    cudaGetSymbolAddress((void**)&y, g_y);
    int* counts = nullptr; cudaGetSymbolAddress((void**)&counts, g_counts);

    cudaMemsetAsync(counts, 0, PT * sizeof(int));

    prep_kernel<<<64, 256>>>(W);

    cudaFuncSetAttribute(mma_gemm_kernel,
                         cudaFuncAttributeMaxDynamicSharedMemorySize, GEMM_SMEM);
    const int gemm_blocks = (NROWS + 127) / 128;        // 313
    mma_gemm_kernel<<<gemm_blocks, 256, GEMM_SMEM>>>(x1, y);

    hist_kernel<<<(PM + 255) / 256, 256>>>(edge);
    scan_kernel<<<1, 1024>>>();
    fill_kernel<<<(PM + 255) / 256, 256>>>(edge);

    gather_kernel<<<NROWS / 8, 256>>>(edge, A, bias, y, out);
}

// round 9
// speedup vs baseline: 1.8930x; 1.1906x over previous
#include <cuda_runtime.h>
#include <cuda_bf16.h>
#include <cstdint>

#define PB    2
#define PT    10000
#define PM    100000
#define PD    128
#define PDOUT 128
#define NROWS (PB * PT * 2)   // 40000

#define WPAD 136              // padded row length (bf16) -> 272 B rows, conflict-free ldmatrix

// ---------------------------------------------------------------------------
// Device scratch (no allocation allowed)
// ---------------------------------------------------------------------------
__device__ float g_y[NROWS * PDOUT];                         // bias-free x@W^T
__device__ __align__(16) __nv_bfloat16 g_Whi[PDOUT * WPAD];
__device__ __align__(16) __nv_bfloat16 g_Wlo[PDOUT * WPAD];
__device__ int g_counts[PT];
__device__ int g_offsets[PT + 1];
__device__ int g_cursor[PT];
__device__ int g_eidx[PM];
__device__ int g_bagg[64];
__device__ unsigned g_bar;          // grid-barrier counter, reset by prep each replay

// ---------------------------------------------------------------------------
// Warp MMA helpers (sm_80-baseline; valid in family-generic compute_103 PTX)
// ---------------------------------------------------------------------------
__device__ __forceinline__ uint32_t smem_u32(const void* p) {
    uint32_t a;
    asm("{ .reg .u64 t; cvta.to.shared.u64 t, %1; cvt.u32.u64 %0, t; }" : "=r"(a) : "l"(p));
    return a;
}
__device__ __forceinline__ void ldsm_x4(uint32_t* r, uint32_t addr) {
    asm volatile("ldmatrix.sync.aligned.m8n8.x4.shared.b16 {%0,%1,%2,%3}, [%4];"
                 : "=r"(r[0]), "=r"(r[1]), "=r"(r[2]), "=r"(r[3]) : "r"(addr));
}
__device__ __forceinline__ void ldsm_x2(uint32_t* r, uint32_t addr) {
    asm volatile("ldmatrix.sync.aligned.m8n8.x2.shared.b16 {%0,%1}, [%2];"
                 : "=r"(r[0]), "=r"(r[1]) : "r"(addr));
}
__device__ __forceinline__ void mma_bf16(float* c, const uint32_t* a, const uint32_t* b) {
    asm volatile("mma.sync.aligned.m16n8k16.row.col.f32.bf16.bf16.f32 "
                 "{%0,%1,%2,%3}, {%4,%5,%6,%7}, {%8,%9}, {%0,%1,%2,%3};"
                 : "+f"(c[0]), "+f"(c[1]), "+f"(c[2]), "+f"(c[3])
                 : "r"(a[0]), "r"(a[1]), "r"(a[2]), "r"(a[3]), "r"(b[0]), "r"(b[1]));
}

// ---------------------------------------------------------------------------
// Prep (fused): blocks 0..63 split W into bf16 hi/lo images;
// blocks 64..454 histogram node_in. Also resets the grid-barrier counter.
// (g_counts zeroed by the preceding memsetAsync.)
// ---------------------------------------------------------------------------
__global__ __launch_bounds__(256) void prep_kernel(
    const float* __restrict__ W, const int* __restrict__ edge)
{
    const int bid = blockIdx.x, tid = threadIdx.x;
    if (bid == 0 && tid == 0) g_bar = 0u;
    if (bid < 64) {
        int idx = bid * 256 + tid;                 // < 16384
        int o = idx >> 7, d = idx & 127;
        float w = W[idx];
        __nv_bfloat16 hi = __float2bfloat16(w);
        __nv_bfloat16 lo = __float2bfloat16(w - __bfloat162float(hi));
        g_Whi[o * WPAD + d] = hi;
        g_Wlo[o * WPAD + d] = lo;
    } else {
        int m = (bid - 64) * 256 + tid;
        if (m < PM) atomicAdd(&g_counts[edge[m]], 1);
    }
}

// ---------------------------------------------------------------------------
// GEMM: y = x @ W^T via mma.sync bf16 split (hi*hi + hi*lo + lo*hi).
// ---------------------------------------------------------------------------
#define SM_XHI 0
#define SM_XLO 34816          // 128*272
#define SM_WHI 69632
#define SM_WLO 104448
#define GEMM_SMEM 139264

__global__ __launch_bounds__(256, 1) void mma_gemm_kernel(
    const float* __restrict__ x, float* __restrict__ y)
{
    extern __shared__ char smem[];
    const uint32_t sb = smem_u32(smem);
    const int tid = threadIdx.x, wid = tid >> 5, lane = tid & 31;
    const int row0 = blockIdx.x * 128;

    {
        const uint4* shi = (const uint4*)g_Whi;
        const uint4* slo = (const uint4*)g_Wlo;
        uint4* dhi = (uint4*)(smem + SM_WHI);
        uint4* dlo = (uint4*)(smem + SM_WLO);
#pragma unroll
        for (int i = tid; i < 2176; i += 256) { dhi[i] = shi[i]; dlo[i] = slo[i]; }
    }
    {
#pragma unroll
        for (int i = 0; i < 16; i++) {
            const int idx = i * 256 + tid;
            const int r = idx >> 5, q = idx & 31;
            const int grow = row0 + r;
            float4 v = make_float4(0.f, 0.f, 0.f, 0.f);
            if (grow < NROWS) v = *(const float4*)(x + (size_t)grow * PD + q * 4);

            __nv_bfloat162 h01 = __float22bfloat162_rn(make_float2(v.x, v.y));
            __nv_bfloat162 h23 = __float22bfloat162_rn(make_float2(v.z, v.w));
            float2 f01 = __bfloat1622float2(h01);
            float2 f23 = __bfloat1622float2(h23);
            __nv_bfloat162 l01 = __float22bfloat162_rn(make_float2(v.x - f01.x, v.y - f01.y));
            __nv_bfloat162 l23 = __float22bfloat162_rn(make_float2(v.z - f23.x, v.w - f23.y));

            const int boff = r * 272 + q * 8;
            *(uint2*)(smem + SM_XHI + boff) = make_uint2(*(uint32_t*)&h01, *(uint32_t*)&h23);
            *(uint2*)(smem + SM_XLO + boff) = make_uint2(*(uint32_t*)&l01, *(uint32_t*)&l23);
        }
    }
    __syncthreads();

    const int wm = wid & 1, wn = wid >> 1;
    const int m_base = wm * 64, n_base = wn * 32;

    float acc[4][4][4];
#pragma unroll
    for (int mt = 0; mt < 4; mt++)
#pragma unroll
        for (int nt = 0; nt < 4; nt++)
#pragma unroll
            for (int j = 0; j < 4; j++) acc[mt][nt][j] = 0.f;

    const int g  = lane >> 3;
    const int lr = lane & 7;

#pragma unroll
    for (int ks = 0; ks < 8; ks++) {
        const int k0 = ks * 16;
        uint32_t bh[4][2], bl[4][2];
#pragma unroll
        for (int nt = 0; nt < 4; nt++) {
            const int nrow = n_base + nt * 8 + lr;
            const int ncol = k0 + ((lane >> 3) & 1) * 8;
            const uint32_t off = (uint32_t)(nrow * 272 + ncol * 2);
            ldsm_x2(bh[nt], sb + SM_WHI + off);
            ldsm_x2(bl[nt], sb + SM_WLO + off);
        }
#pragma unroll
        for (int mt = 0; mt < 4; mt++) {
            const int arow = m_base + mt * 16 + (g & 1) * 8 + lr;
            const int acol = k0 + (g >> 1) * 8;
            const uint32_t off = (uint32_t)(arow * 272 + acol * 2);
            uint32_t ah[4], al[4];
            ldsm_x4(ah, sb + SM_XHI + off);
            ldsm_x4(al, sb + SM_XLO + off);
#pragma unroll
            for (int nt = 0; nt < 4; nt++) {
                mma_bf16(acc[mt][nt], ah, bh[nt]);
                mma_bf16(acc[mt][nt], ah, bl[nt]);
                mma_bf16(acc[mt][nt], al, bh[nt]);
            }
        }
    }

    const int erow = m_base + (lane >> 2);
    const int ecol = (lane & 3) * 2;
#pragma unroll
    for (int mt = 0; mt < 4; mt++) {
        const int r0 = row0 + erow + mt * 16;
#pragma unroll
        for (int nt = 0; nt < 4; nt++) {
            const int col = n_base + nt * 8 + ecol;
            if (r0 < NROWS)
                *(float2*)(y + (size_t)r0 * PDOUT + col) =
                    make_float2(acc[mt][nt][0], acc[mt][nt][1]);
            if (r0 + 8 < NROWS)
                *(float2*)(y + (size_t)(r0 + 8) * PDOUT + col) =
                    make_float2(acc[mt][nt][2], acc[mt][nt][3]);
        }
    }
}

// ---------------------------------------------------------------------------
// Fused scan + fill: 40 blocks x 256 threads, two software grid barriers.
// Phase 1: block-local exclusive scan of counts (1 elem/thread).
// Phase 2: add prefix of block aggregates; write offsets + cursor.
// Phase 3: grid-stride counting-sort fill of g_eidx.
// ---------------------------------------------------------------------------
#define SCAN_BLOCKS 40

__device__ __forceinline__ void grid_barrier(unsigned target, int tid) {
    __threadfence();
    __syncthreads();
    if (tid == 0) {
        atomicAdd(&g_bar, 1u);
        while (*(volatile unsigned*)&g_bar < target) { }
    }
    __syncthreads();
    __threadfence();
}

__global__ __launch_bounds__(256) void scanfill_kernel(const int* __restrict__ edge)
{
    const int tid = threadIdx.x, b = blockIdx.x;
    const int lane = tid & 31, wid = tid >> 5;
    const int idx = b * 256 + tid;

    // ---- Phase 1: block scan ----
    const int v = (idx < PT) ? g_counts[idx] : 0;
    int inc = v;
#pragma unroll
    for (int d = 1; d < 32; d <<= 1) {
        int n = __shfl_up_sync(0xffffffffu, inc, d);
        if (lane >= d) inc += n;
    }
    __shared__ int ws[8], wexcl[8];
    if (lane == 31) ws[wid] = inc;
    __syncthreads();
    if (tid == 0) {
        int s = 0;
#pragma unroll
        for (int i = 0; i < 8; i++) { wexcl[i] = s; s += ws[i]; }
        g_bagg[b] = s;                       // block aggregate
    }
    __syncthreads();
    const int excl = wexcl[wid] + (inc - v); // block-local exclusive prefix

    grid_barrier(SCAN_BLOCKS, tid);

    // ---- Phase 2: global offsets ----
    __shared__ int boff_s;
    if (tid == 0) {
        int s = 0;
        for (int i = 0; i < b; i++) s += g_bagg[i];
        boff_s = s;
    }
    __syncthreads();
    const int off = boff_s + excl;
    if (idx < PT) { g_offsets[idx] = off; g_cursor[idx] = off; }
    if (b == SCAN_BLOCKS - 1 && tid == 255) g_offsets[PT] = off + v;  // == PM

    grid_barrier(2 * SCAN_BLOCKS, tid);

    // ---- Phase 3: fill ----
    for (int m = b * 256 + tid; m < PM; m += SCAN_BLOCKS * 256) {
        int pos = atomicAdd(&g_cursor[edge[m]], 1);
        g_eidx[pos] = m;
    }
}

// ---------------------------------------------------------------------------
// Gather-reduce: one warp per node t. Accumulates all 4 (b,c) rows at once;
// edge metadata loaded once per edge (warp-uniform broadcast).
// ---------------------------------------------------------------------------
__global__ __launch_bounds__(256) void gather_kernel(
    const int*   __restrict__ edge,
    const float* __restrict__ A,
    const float* __restrict__ bias,
    const float* __restrict__ y,
    float*       __restrict__ out)
{
    const unsigned t = blockIdx.x * 8u + (threadIdx.x >> 5);   // 0..PT-1 exact
    const int lane = threadIdx.x & 31;

    const float4 b4 = ((const float4*)bias)[lane];

    // Row indices for (b, c) combos of this node
    const size_t r00 = ((size_t)(t << 1)) << 7;                      // b0 c0
    const size_t r01 = r00 + 128;                                    // b0 c1
    const size_t r10 = ((size_t)((PT + t) << 1)) << 7;               // b1 c0
    const size_t r11 = r10 + 128;                                    // b1 c1

    float4 a00 = ((const float4*)(y + r00))[lane];
    float4 a01 = ((const float4*)(y + r01))[lane];
    float4 a10 = ((const float4*)(y + r10))[lane];
    float4 a11 = ((const float4*)(y + r11))[lane];
    a00.x += b4.x; a00.y += b4.y; a00.z += b4.z; a00.w += b4.w;
    a01.x += b4.x; a01.y += b4.y; a01.z += b4.z; a01.w += b4.w;
    a10.x += b4.x; a10.y += b4.y; a10.z += b4.z; a10.w += b4.w;
    a11.x += b4.x; a11.y += b4.y; a11.z += b4.z; a11.w += b4.w;

    const int s = g_offsets[t];
    const int e = g_offsets[t + 1];
    for (int p = s; p < e; p++) {
        const int   m  = g_eidx[p];                 // warp-uniform
        const int   no = __ldg(edge + PM + m);
        const float w0 = __ldg(A + m);
        const float w1 = __ldg(A + PM + m);

        const size_t s00 = ((size_t)((unsigned)no << 1)) << 7;
        const size_t s10 = ((size_t)((PT + (unsigned)no) << 1)) << 7;
        const float4 v00 = ((const float4*)(y + s00))[lane];
        const float4 v01 = ((const float4*)(y + s00 + 128))[lane];
        const float4 v10 = ((const float4*)(y + s10))[lane];
        const float4 v11 = ((const float4*)(y + s10 + 128))[lane];

        a00.x += w0 * v00.x; a00.y += w0 * v00.y; a00.z += w0 * v00.z; a00.w += w0 * v00.w;
        a01.x += w0 * v01.x; a01.y += w0 * v01.y; a01.z += w0 * v01.z; a01.w += w0 * v01.w;
        a10.x += w1 * v10.x; a10.y += w1 * v10.y; a10.z += w1 * v10.z; a10.w += w1 * v10.w;
        a11.x += w1 * v11.x; a11.y += w1 * v11.y; a11.z += w1 * v11.z; a11.w += w1 * v11.w;
    }

    ((float4*)(out + r00))[lane] = a00;
    ((float4*)(out + r01))[lane] = a01;
    ((float4*)(out + r10))[lane] = a10;
    ((float4*)(out + r11))[lane] = a11;
}

// ---------------------------------------------------------------------------
// Launch. Inputs: [0] x_1st, [1] x_2nd (unused), [2] edge, [3] A_masked,
//                 [4] W, [5] b
// ---------------------------------------------------------------------------
extern "C" void kernel_launch(void* const* d_in, const int* in_sizes, int n_in,
                              void* d_out, int out_size)
{
    const float* x1   = (const float*)d_in[0];
    const int*   edge = (const int*)  d_in[2];
    const float* A    = (const float*)d_in[3];
    const float* W    = (const float*)d_in[4];
    const float* bias = (const float*)d_in[5];
    float*       out  = (float*)d_out;

    float* y = nullptr;    cudaGetSymbolAddress((void**)&y, g_y);
    int* counts = nullptr; cudaGetSymbolAddress((void**)&counts, g_counts);

    cudaMemsetAsync(counts, 0, PT * sizeof(int));

    prep_kernel<<<64 + (PM + 255) / 256, 256>>>(W, edge);

    cudaFuncSetAttribute(mma_gemm_kernel,
                         cudaFuncAttributeMaxDynamicSharedMemorySize, GEMM_SMEM);
    mma_gemm_kernel<<<(NROWS + 127) / 128, 256, GEMM_SMEM>>>(x1, y);

    scanfill_kernel<<<SCAN_BLOCKS, 256>>>(edge);

    gather_kernel<<<PT / 8, 256>>>(edge, A, bias, y, out);
}

// round 12
// speedup vs baseline: 2.0130x; 1.0634x over previous
#include <cuda_runtime.h>
#include <cuda_bf16.h>
#include <cstdint>

#define PB    2
#define PT    10000
#define PM    100000
#define PD    128
#define PDOUT 128
#define NROWS (PB * PT * 2)   // 40000

#define WPAD 136              // padded row length (bf16) -> 272 B rows, conflict-free ldmatrix

// ---------------------------------------------------------------------------
// Device scratch (no allocation allowed; zero-initialized at module load)
// ---------------------------------------------------------------------------
__device__ float g_y[NROWS * PDOUT];                         // bias-free x@W^T
__device__ __align__(16) __nv_bfloat16 g_Whi[PDOUT * WPAD];
__device__ __align__(16) __nv_bfloat16 g_Wlo[PDOUT * WPAD];
__device__ int g_counts[PT];        // zeroed at load; re-zeroed by scanfill each run
__device__ int g_offsets[PT + 1];
__device__ int g_cursor[PT];
__device__ __align__(16) float4 g_edata[PM];   // {bits(node_out), w_b0, w_b1, 0}
__device__ int g_bagg[128];
__device__ unsigned g_bar;          // grid-barrier counter, reset by prep each replay

// ---------------------------------------------------------------------------
// Warp MMA helpers (sm_80-baseline; valid in family-generic compute_103 PTX)
// ---------------------------------------------------------------------------
__device__ __forceinline__ uint32_t smem_u32(const void* p) {
    uint32_t a;
    asm("{ .reg .u64 t; cvta.to.shared.u64 t, %1; cvt.u32.u64 %0, t; }" : "=r"(a) : "l"(p));
    return a;
}
__device__ __forceinline__ void ldsm_x4(uint32_t* r, uint32_t addr) {
    asm volatile("ldmatrix.sync.aligned.m8n8.x4.shared.b16 {%0,%1,%2,%3}, [%4];"
                 : "=r"(r[0]), "=r"(r[1]), "=r"(r[2]), "=r"(r[3]) : "r"(addr));
}
__device__ __forceinline__ void ldsm_x2(uint32_t* r, uint32_t addr) {
    asm volatile("ldmatrix.sync.aligned.m8n8.x2.shared.b16 {%0,%1}, [%2];"
                 : "=r"(r[0]), "=r"(r[1]) : "r"(addr));
}
__device__ __forceinline__ void mma_bf16(float* c, const uint32_t* a, const uint32_t* b) {
    asm volatile("mma.sync.aligned.m16n8k16.row.col.f32.bf16.bf16.f32 "
                 "{%0,%1,%2,%3}, {%4,%5,%6,%7}, {%8,%9}, {%0,%1,%2,%3};"
                 : "+f"(c[0]), "+f"(c[1]), "+f"(c[2]), "+f"(c[3])
                 : "r"(a[0]), "r"(a[1]), "r"(a[2]), "r"(a[3]), "r"(b[0]), "r"(b[1]));
}

// ---------------------------------------------------------------------------
// Prep (fused): blocks 0..63 split W into bf16 hi/lo images;
// blocks 64.. histogram node_in. Resets the grid-barrier counter.
// g_counts is zero on entry (module-load zero-init, then re-zeroed by the
// previous run's scanfill phase 3).
// ---------------------------------------------------------------------------
__global__ __launch_bounds__(256) void prep_kernel(
    const float* __restrict__ W, const int* __restrict__ edge)
{
    const int bid = blockIdx.x, tid = threadIdx.x;
    if (bid == 0 && tid == 0) g_bar = 0u;
    if (bid < 64) {
        int idx = bid * 256 + tid;                 // < 16384
        int o = idx >> 7, d = idx & 127;
        float w = W[idx];
        __nv_bfloat16 hi = __float2bfloat16(w);
        __nv_bfloat16 lo = __float2bfloat16(w - __bfloat162float(hi));
        g_Whi[o * WPAD + d] = hi;
        g_Wlo[o * WPAD + d] = lo;
    } else {
        int m = (bid - 64) * 256 + tid;
        if (m < PM) atomicAdd(&g_counts[edge[m]], 1);
    }
}

// ---------------------------------------------------------------------------
// GEMM: y = x @ W^T via mma.sync bf16 split (hi*hi + hi*lo + lo*hi).
// ---------------------------------------------------------------------------
#define SM_XHI 0
#define SM_XLO 34816          // 128*272
#define SM_WHI 69632
#define SM_WLO 104448
#define GEMM_SMEM 139264

__global__ __launch_bounds__(256, 1) void mma_gemm_kernel(
    const float* __restrict__ x, float* __restrict__ y)
{
    extern __shared__ char smem[];
    const uint32_t sb = smem_u32(smem);
    const int tid = threadIdx.x, wid = tid >> 5, lane = tid & 31;
    const int row0 = blockIdx.x * 128;

    {
        const uint4* shi = (const uint4*)g_Whi;
        const uint4* slo = (const uint4*)g_Wlo;
        uint4* dhi = (uint4*)(smem + SM_WHI);
        uint4* dlo = (uint4*)(smem + SM_WLO);
#pragma unroll
        for (int i = tid; i < 2176; i += 256) { dhi[i] = shi[i]; dlo[i] = slo[i]; }
    }
    {
#pragma unroll
        for (int i = 0; i < 16; i++) {
            const int idx = i * 256 + tid;
            const int r = idx >> 5, q = idx & 31;
            const int grow = row0 + r;
            float4 v = make_float4(0.f, 0.f, 0.f, 0.f);
            if (grow < NROWS) v = *(const float4*)(x + (size_t)grow * PD + q * 4);

            __nv_bfloat162 h01 = __float22bfloat162_rn(make_float2(v.x, v.y));
            __nv_bfloat162 h23 = __float22bfloat162_rn(make_float2(v.z, v.w));
            float2 f01 = __bfloat1622float2(h01);
            float2 f23 = __bfloat1622float2(h23);
            __nv_bfloat162 l01 = __float22bfloat162_rn(make_float2(v.x - f01.x, v.y - f01.y));
            __nv_bfloat162 l23 = __float22bfloat162_rn(make_float2(v.z - f23.x, v.w - f23.y));

            const int boff = r * 272 + q * 8;
            *(uint2*)(smem + SM_XHI + boff) = make_uint2(*(uint32_t*)&h01, *(uint32_t*)&h23);
            *(uint2*)(smem + SM_XLO + boff) = make_uint2(*(uint32_t*)&l01, *(uint32_t*)&l23);
        }
    }
    __syncthreads();

    const int wm = wid & 1, wn = wid >> 1;
    const int m_base = wm * 64, n_base = wn * 32;

    float acc[4][4][4];
#pragma unroll
    for (int mt = 0; mt < 4; mt++)
#pragma unroll
        for (int nt = 0; nt < 4; nt++)
#pragma unroll
            for (int j = 0; j < 4; j++) acc[mt][nt][j] = 0.f;

    const int g  = lane >> 3;
    const int lr = lane & 7;

#pragma unroll
    for (int ks = 0; ks < 8; ks++) {
        const int k0 = ks * 16;
        uint32_t bh[4][2], bl[4][2];
#pragma unroll
        for (int nt = 0; nt < 4; nt++) {
            const int nrow = n_base + nt * 8 + lr;
            const int ncol = k0 + ((lane >> 3) & 1) * 8;
            const uint32_t off = (uint32_t)(nrow * 272 + ncol * 2);
            ldsm_x2(bh[nt], sb + SM_WHI + off);
            ldsm_x2(bl[nt], sb + SM_WLO + off);
        }
#pragma unroll
        for (int mt = 0; mt < 4; mt++) {
            const int arow = m_base + mt * 16 + (g & 1) * 8 + lr;
            const int acol = k0 + (g >> 1) * 8;
            const uint32_t off = (uint32_t)(arow * 272 + acol * 2);
            uint32_t ah[4], al[4];
            ldsm_x4(ah, sb + SM_XHI + off);
            ldsm_x4(al, sb + SM_XLO + off);
#pragma unroll
            for (int nt = 0; nt < 4; nt++) {
                mma_bf16(acc[mt][nt], ah, bh[nt]);
                mma_bf16(acc[mt][nt], ah, bl[nt]);
                mma_bf16(acc[mt][nt], al, bh[nt]);
            }
        }
    }

    const int erow = m_base + (lane >> 2);
    const int ecol = (lane & 3) * 2;
#pragma unroll
    for (int mt = 0; mt < 4; mt++) {
        const int r0 = row0 + erow + mt * 16;
#pragma unroll
        for (int nt = 0; nt < 4; nt++) {
            const int col = n_base + nt * 8 + ecol;
            if (r0 < NROWS)
                *(float2*)(y + (size_t)r0 * PDOUT + col) =
                    make_float2(acc[mt][nt][0], acc[mt][nt][1]);
            if (r0 + 8 < NROWS)
                *(float2*)(y + (size_t)(r0 + 8) * PDOUT + col) =
                    make_float2(acc[mt][nt][2], acc[mt][nt][3]);
        }
    }
}

// ---------------------------------------------------------------------------
// Fused scan + fill: 128 blocks x 256 threads, two software grid barriers.
// Phase 1: block-local exclusive scan of counts.
// Phase 2: add prefix of block aggregates; write offsets + cursor.
// Phase 3: counting-sort fill of flattened edge payload g_edata
//          {bits(node_out), A[b0], A[b1]} and re-zero g_counts for next run.
// ---------------------------------------------------------------------------
#define SCAN_BLOCKS 128

__device__ __forceinline__ void grid_barrier(unsigned target, int tid) {
    __threadfence();
    __syncthreads();
    if (tid == 0) {
        atomicAdd(&g_bar, 1u);
        while (*(volatile unsigned*)&g_bar < target) { }
    }
    __syncthreads();
    __threadfence();
}

__global__ __launch_bounds__(256) void scanfill_kernel(
    const int* __restrict__ edge, const float* __restrict__ A)
{
    const int tid = threadIdx.x, b = blockIdx.x;
    const int lane = tid & 31, wid = tid >> 5;
    const int idx = b * 256 + tid;

    // ---- Phase 1: block scan ----
    const int v = (idx < PT) ? g_counts[idx] : 0;
    int inc = v;
#pragma unroll
    for (int d = 1; d < 32; d <<= 1) {
        int n = __shfl_up_sync(0xffffffffu, inc, d);
        if (lane >= d) inc += n;
    }
    __shared__ int ws[8], wexcl[8];
    if (lane == 31) ws[wid] = inc;
    __syncthreads();
    if (tid == 0) {
        int s = 0;
#pragma unroll
        for (int i = 0; i < 8; i++) { wexcl[i] = s; s += ws[i]; }
        g_bagg[b] = s;
    }
    __syncthreads();
    const int excl = wexcl[wid] + (inc - v);

    grid_barrier(SCAN_BLOCKS, tid);

    // ---- Phase 2: global offsets ----
    __shared__ int boff_s;
    if (tid == 0) {
        int s = 0;
#pragma unroll 8
        for (int i = 0; i < b; i++) s += g_bagg[i];
        boff_s = s;
    }
    __syncthreads();
    const int off = boff_s + excl;
    if (idx < PT) { g_offsets[idx] = off; g_cursor[idx] = off; }
    if (b == SCAN_BLOCKS - 1 && tid == 255) g_offsets[PT] = off + v;  // == PM

    grid_barrier(2 * SCAN_BLOCKS, tid);

    // ---- Phase 3: fill flattened payload + re-zero counts ----
    for (int m = idx; m < PM; m += SCAN_BLOCKS * 256) {
        const int   ni = edge[m];
        const int   no = edge[PM + m];
        const float w0 = A[m];
        const float w1 = A[PM + m];
        int pos = atomicAdd(&g_cursor[ni], 1);
        g_edata[pos] = make_float4(__int_as_float(no), w0, w1, 0.f);
    }
    for (int i = idx; i < PT; i += SCAN_BLOCKS * 256) g_counts[i] = 0;
}

// ---------------------------------------------------------------------------
// Gather-reduce: one warp per node t, all 4 (b,c) rows at once.
// Flattened edata: single sequential load per edge (no indirection chain).
// ---------------------------------------------------------------------------
__global__ __launch_bounds__(256) void gather_kernel(
    const float* __restrict__ bias,
    const float* __restrict__ y,
    float*       __restrict__ out)
{
    const unsigned t = blockIdx.x * 8u + (threadIdx.x >> 5);   // 0..PT-1 exact
    const int lane = threadIdx.x & 31;

    const float4 b4 = ((const float4*)bias)[lane];

    const size_t r00 = ((size_t)(t << 1)) << 7;            // b0 c0
    const size_t r10 = ((size_t)((PT + t) << 1)) << 7;     // b1 c0

    float4 a00 = ((const float4*)(y + r00))[lane];
    float4 a01 = ((const float4*)(y + r00 + 128))[lane];
    float4 a10 = ((const float4*)(y + r10))[lane];
    float4 a11 = ((const float4*)(y + r10 + 128))[lane];
    a00.x += b4.x; a00.y += b4.y; a00.z += b4.z; a00.w += b4.w;
    a01.x += b4.x; a01.y += b4.y; a01.z += b4.z; a01.w += b4.w;
    a10.x += b4.x; a10.y += b4.y; a10.z += b4.z; a10.w += b4.w;
    a11.x += b4.x; a11.y += b4.y; a11.z += b4.z; a11.w += b4.w;

    const int s = g_offsets[t];
    const int e = g_offsets[t + 1];
    int p = s;

    for (; p + 2 <= e; p += 2) {
        const float4 e0 = __ldg(&g_edata[p]);
        const float4 e1 = __ldg(&g_edata[p + 1]);
        const unsigned n0 = (unsigned)__float_as_int(e0.x);
        const unsigned n1 = (unsigned)__float_as_int(e1.x);

        const size_t s0 = ((size_t)(n0 << 1)) << 7;
        const size_t t0 = ((size_t)((PT + n0) << 1)) << 7;
        const size_t s1 = ((size_t)(n1 << 1)) << 7;
        const size_t t1 = ((size_t)((PT + n1) << 1)) << 7;

        const float4 v00a = ((const float4*)(y + s0))[lane];
        const float4 v01a = ((const float4*)(y + s0 + 128))[lane];
        const float4 v10a = ((const float4*)(y + t0))[lane];
        const float4 v11a = ((const float4*)(y + t0 + 128))[lane];
        const float4 v00b = ((const float4*)(y + s1))[lane];
        const float4 v01b = ((const float4*)(y + s1 + 128))[lane];
        const float4 v10b = ((const float4*)(y + t1))[lane];
        const float4 v11b = ((const float4*)(y + t1 + 128))[lane];

        a00.x += e0.y * v00a.x; a00.y += e0.y * v00a.y; a00.z += e0.y * v00a.z; a00.w += e0.y * v00a.w;
        a01.x += e0.y * v01a.x; a01.y += e0.y * v01a.y; a01.z += e0.y * v01a.z; a01.w += e0.y * v01a.w;
        a10.x += e0.z * v10a.x; a10.y += e0.z * v10a.y; a10.z += e0.z * v10a.z; a10.w += e0.z * v10a.w;
        a11.x += e0.z * v11a.x; a11.y += e0.z * v11a.y; a11.z += e0.z * v11a.z; a11.w += e0.z * v11a.w;

        a00.x += e1.y * v00b.x; a00.y += e1.y * v00b.y; a00.z += e1.y * v00b.z; a00.w += e1.y * v00b.w;
        a01.x += e1.y * v01b.x; a01.y += e1.y * v01b.y; a01.z += e1.y * v01b.z; a01.w += e1.y * v01b.w;
        a10.x += e1.z * v10b.x; a10.y += e1.z * v10b.y; a10.z += e1.z * v10b.z; a10.w += e1.z * v10b.w;
        a11.x += e1.z * v11b.x; a11.y += e1.z * v11b.y; a11.z += e1.z * v11b.z; a11.w += e1.z * v11b.w;
    }
    if (p < e) {
        const float4 e0 = __ldg(&g_edata[p]);
        const unsigned n0 = (unsigned)__float_as_int(e0.x);
        const size_t s0 = ((size_t)(n0 << 1)) << 7;
        const size_t t0 = ((size_t)((PT + n0) << 1)) << 7;
        const float4 v00 = ((const float4*)(y + s0))[lane];
        const float4 v01 = ((const float4*)(y + s0 + 128))[lane];
        const float4 v10 = ((const float4*)(y + t0))[lane];
        const float4 v11 = ((const float4*)(y + t0 + 128))[lane];
        a00.x += e0.y * v00.x; a00.y += e0.y * v00.y; a00.z += e0.y * v00.z; a00.w += e0.y * v00.w;
        a01.x += e0.y * v01.x; a01.y += e0.y * v01.y; a01.z += e0.y * v01.z; a01.w += e0.y * v01.w;
        a10.x += e0.z * v10.x; a10.y += e0.z * v10.y; a10.z += e0.z * v10.z; a10.w += e0.z * v10.w;
        a11.x += e0.z * v11.x; a11.y += e0.z * v11.y; a11.z += e0.z * v11.z; a11.w += e0.z * v11.w;
    }

    ((float4*)(out + r00))[lane]       = a00;
    ((float4*)(out + r00 + 128))[lane] = a01;
    ((float4*)(out + r10))[lane]       = a10;
    ((float4*)(out + r10 + 128))[lane] = a11;
}

// ---------------------------------------------------------------------------
// Launch. Inputs: [0] x_1st, [1] x_2nd (unused), [2] edge, [3] A_masked,
//                 [4] W, [5] b
// ---------------------------------------------------------------------------
extern "C" void kernel_launch(void* const* d_in, const int* in_sizes, int n_in,
                              void* d_out, int out_size)
{
    const float* x1   = (const float*)d_in[0];
    const int*   edge = (const int*)  d_in[2];
    const float* A    = (const float*)d_in[3];
    const float* W    = (const float*)d_in[4];
    const float* bias = (const float*)d_in[5];
    float*       out  = (float*)d_out;

    float* y = nullptr; cudaGetSymbolAddress((void**)&y, g_y);

    prep_kernel<<<64 + (PM + 255) / 256, 256>>>(W, edge);

    cudaFuncSetAttribute(mma_gemm_kernel,
                         cudaFuncAttributeMaxDynamicSharedMemorySize, GEMM_SMEM);
    mma_gemm_kernel<<<(NROWS + 127) / 128, 256, GEMM_SMEM>>>(x1, y);

    scanfill_kernel<<<SCAN_BLOCKS, 256>>>(edge, A);

    gather_kernel<<<PT / 8, 256>>>(bias, y, out);
}